// round 7
// baseline (speedup 1.0000x reference)
#include <cuda_runtime.h>
#include <math.h>

// Problem constants: T=768, B=4, E=256, H=8, HD=32, 32 "bh" heads.
// Q scale folded with log2(e): scores arrive in log2 domain, exp(s) == 2^s'.
#define QSCALE 0.25500917392938054f   // (1/sqrt(32)) * log2(e)

// ---------------- scratch (static device globals; no allocation) ----------------
__device__ float g_q[786432];        // [bh=32][t=768][hd=32]
__device__ float g_k[786432];
__device__ float g_v[786432];
__device__ float g_obuf[5505024];    // [branch=7][bh=32][t=768][hd=32]
__device__ float g_G[458752];        // [7][y=256][x=256]
__device__ float g_tmpT[458752];     // [7][a=256][y=256]
__device__ float g_MTcat[458752];    // [n=256][k=1792]
__device__ float g_c1[256];
__device__ float g_biasv[256];

// Segments partition the columns: L=[0,300) A=[300,550) V=[550,768)
__constant__ int c_segS[3] = {0, 300, 550};
__constant__ int c_segE[3] = {300, 550, 768};
// branch -> segment bitmask: lav, la, lv, av, l, a, v
__constant__ int c_bmask[7] = {7, 3, 5, 6, 1, 2, 4};

// FMA-pipe 2^x (no MUFU). |x| < ~80, rel err ~1e-7 (deg-6 Taylor on [-0.5,0.5]).
__device__ __forceinline__ float fexp2(float x)
{
    float z = x + 12582912.0f;            // 1.5*2^23: round-to-nearest-int trick
    int   n = __float_as_int(z);          // low bits hold round(x)
    float f = x - (z - 12582912.0f);      // frac in [-0.5, 0.5], exact
    float p = 1.5402387e-4f;
    p = fmaf(p, f, 1.3333558e-3f);
    p = fmaf(p, f, 9.6181291e-3f);
    p = fmaf(p, f, 5.5504109e-2f);
    p = fmaf(p, f, 2.4022651e-1f);
    p = fmaf(p, f, 6.9314718e-1f);
    p = fmaf(p, f, 1.0f);
    return __int_as_float(__float_as_int(p) + (n << 23));
}

// ---------------- small tiled SGEMM (32x32 tiles), per-operand coalesced loads ----------------
__global__ void __launch_bounds__(256) gemm_small(
    const float* __restrict__ A, int a_sm, int a_sk, int a_bz,
    const float* __restrict__ B, int b_sn, int b_sk, int b_bz,
    float* __restrict__ C, int c_sm, int c_bz,
    int K)
{
    A += (size_t)blockIdx.z * a_bz;
    B += (size_t)blockIdx.z * b_bz;
    C += (size_t)blockIdx.z * c_bz;
    int m0 = blockIdx.y * 32, n0 = blockIdx.x * 32;
    __shared__ float As[16][36], Bs[16][36];
    int tid = threadIdx.x;
    int tx = tid & 15, ty = tid >> 4;
    float acc[2][2] = {};
    for (int k0 = 0; k0 < K; k0 += 16) {
        if (a_sk == 1) {
            #pragma unroll
            for (int i = 0; i < 2; i++) {
                int idx = tid + i * 256;
                int mm = idx >> 4, kk = idx & 15;
                As[kk][mm] = A[(size_t)(m0 + mm) * a_sm + (k0 + kk)];
            }
        } else {
            #pragma unroll
            for (int i = 0; i < 2; i++) {
                int idx = tid + i * 256;
                int mm = idx & 31, kk = idx >> 5;
                As[kk][mm] = A[(size_t)(m0 + mm) + (size_t)(k0 + kk) * a_sk];
            }
        }
        if (b_sk == 1) {
            #pragma unroll
            for (int i = 0; i < 2; i++) {
                int idx = tid + i * 256;
                int mm = idx >> 4, kk = idx & 15;
                Bs[kk][mm] = B[(size_t)(n0 + mm) * b_sn + (k0 + kk)];
            }
        } else {
            #pragma unroll
            for (int i = 0; i < 2; i++) {
                int idx = tid + i * 256;
                int mm = idx & 31, kk = idx >> 5;
                Bs[kk][mm] = B[(size_t)(n0 + mm) + (size_t)(k0 + kk) * b_sk];
            }
        }
        __syncthreads();
        #pragma unroll
        for (int kk = 0; kk < 16; kk++) {
            float2 a = *(const float2*)&As[kk][ty * 2];
            float2 b = *(const float2*)&Bs[kk][tx * 2];
            acc[0][0] = fmaf(a.x, b.x, acc[0][0]);
            acc[0][1] = fmaf(a.x, b.y, acc[0][1]);
            acc[1][0] = fmaf(a.y, b.x, acc[1][0]);
            acc[1][1] = fmaf(a.y, b.y, acc[1][1]);
        }
        __syncthreads();
    }
    #pragma unroll
    for (int i = 0; i < 2; i++)
        #pragma unroll
        for (int j = 0; j < 2; j++)
            C[(size_t)(m0 + ty * 2 + i) * c_sm + (n0 + tx * 2 + j)] = acc[i][j];
}

// ---------------- QKV projection, scattered to head-major ----------------
__global__ void __launch_bounds__(256) proj_kernel(
    const float* __restrict__ q_in, const float* __restrict__ k_in,
    const float* __restrict__ v_in, const float* __restrict__ W,
    const float* __restrict__ bias)
{
    int z = blockIdx.z;
    const float* A = (z == 0) ? q_in : (z == 1) ? k_in : v_in;
    float* dst = (z == 0) ? g_q : (z == 1) ? g_k : g_v;
    const float* Bw = W + (size_t)z * 65536;
    const float* bz = bias + z * 256;
    float scale = (z == 0) ? QSCALE : 1.0f;

    int m0 = blockIdx.y * 64, n0 = blockIdx.x * 64;
    __shared__ float As[16][68], Bs[16][68];
    int tid = threadIdx.x;
    int tx = tid & 15, ty = tid >> 4;
    float acc[4][4] = {};
    for (int k0 = 0; k0 < 256; k0 += 16) {
        #pragma unroll
        for (int i = 0; i < 4; i++) {
            int idx = tid + i * 256;
            int mm = idx >> 4, kk = idx & 15;
            As[kk][mm] = A[(size_t)(m0 + mm) * 256 + (k0 + kk)];
            Bs[kk][mm] = Bw[(size_t)(n0 + mm) * 256 + (k0 + kk)];
        }
        __syncthreads();
        #pragma unroll
        for (int kk = 0; kk < 16; kk++) {
            float4 a = *(const float4*)&As[kk][ty * 4];
            float4 b = *(const float4*)&Bs[kk][tx * 4];
            acc[0][0] = fmaf(a.x, b.x, acc[0][0]);
            acc[0][1] = fmaf(a.x, b.y, acc[0][1]);
            acc[0][2] = fmaf(a.x, b.z, acc[0][2]);
            acc[0][3] = fmaf(a.x, b.w, acc[0][3]);
            acc[1][0] = fmaf(a.y, b.x, acc[1][0]);
            acc[1][1] = fmaf(a.y, b.y, acc[1][1]);
            acc[1][2] = fmaf(a.y, b.z, acc[1][2]);
            acc[1][3] = fmaf(a.y, b.w, acc[1][3]);
            acc[2][0] = fmaf(a.z, b.x, acc[2][0]);
            acc[2][1] = fmaf(a.z, b.y, acc[2][1]);
            acc[2][2] = fmaf(a.z, b.z, acc[2][2]);
            acc[2][3] = fmaf(a.z, b.w, acc[2][3]);
            acc[3][0] = fmaf(a.w, b.x, acc[3][0]);
            acc[3][1] = fmaf(a.w, b.y, acc[3][1]);
            acc[3][2] = fmaf(a.w, b.z, acc[3][2]);
            acc[3][3] = fmaf(a.w, b.w, acc[3][3]);
        }
        __syncthreads();
    }
    #pragma unroll
    for (int i = 0; i < 4; i++) {
        int m = m0 + ty * 4 + i;
        int t = m >> 2, b = m & 3;
        #pragma unroll
        for (int j = 0; j < 4; j++) {
            int n = n0 + tx * 4 + j;
            int h = n >> 5, hd = n & 31;
            float val = (acc[i][j] + bz[n]) * scale;
            dst[(size_t)((b * 8 + h) * 768 + t) * 32 + hd] = val;
        }
    }
}

// ---------------- fully fused flash attention + branch combine ----------------
__global__ void __launch_bounds__(256) flash_kernel()
{
    const int segS[3] = {0, 300, 550};
    const int segE[3] = {300, 550, 768};
    const int bmask[7] = {7, 3, 5, 6, 1, 2, 4};

    int bh = blockIdx.y, t0 = blockIdx.x * 64;
    int tid = threadIdx.x;
    int tx = tid & 15, ty = tid >> 4;   // S mapping: rows ty*4+i, cols tx*4+j
    int h2 = tx * 2;                    // PV mapping: rows ty+16k, hd pair h2

    __shared__ float QsT[32][68], KsT[32][68];
    __shared__ float Ws[64][68];
    __shared__ float Vs[32][68];        // row stride 68 floats = 16B-aligned rows
    __shared__ float sl_s[3][64];
    __shared__ float srd[7][64];

    const float* qbase = g_q + (size_t)bh * 24576 + (size_t)t0 * 32;
    const float* kb = g_k + (size_t)bh * 24576;
    const float* vb = g_v + (size_t)bh * 24576;

    #pragma unroll
    for (int i = 0; i < 8; i++) {
        int idx = tid + i * 256;
        int r = idx >> 5, kk = idx & 31;
        QsT[kk][r] = qbase[r * 32 + kk];
    }

    float acc[3][4][2] = {};

    #pragma unroll
    for (int seg = 0; seg < 3; seg++) {
        int ss = segS[seg], se = segE[seg];
        int ts = ss >> 6, te = (se + 63) >> 6;
        float lpart[4];
        #pragma unroll
        for (int i = 0; i < 4; i++) lpart[i] = 0.0f;

        for (int st = ts; st < te; st++) {
            int s0 = st * 64;
            __syncthreads();
            #pragma unroll
            for (int i = 0; i < 8; i++) {
                int idx = tid + i * 256;
                int r = idx >> 5, kk = idx & 31;
                KsT[kk][r] = kb[(size_t)(s0 + r) * 32 + kk];
            }
            #pragma unroll
            for (int i = 0; i < 8; i++) {
                int idx = tid + i * 256;
                int sc = idx >> 5, hd = idx & 31;
                Vs[hd][sc] = vb[(size_t)(s0 + sc) * 32 + hd];
            }
            __syncthreads();

            // S tile 4x4: rows ty*4+i, cols tx*4+j
            float sv[4][4] = {};
            #pragma unroll
            for (int kk = 0; kk < 32; kk++) {
                float4 a = *(const float4*)&QsT[kk][ty * 4];
                float4 b = *(const float4*)&KsT[kk][tx * 4];
                sv[0][0] = fmaf(a.x, b.x, sv[0][0]);
                sv[0][1] = fmaf(a.x, b.y, sv[0][1]);
                sv[0][2] = fmaf(a.x, b.z, sv[0][2]);
                sv[0][3] = fmaf(a.x, b.w, sv[0][3]);
                sv[1][0] = fmaf(a.y, b.x, sv[1][0]);
                sv[1][1] = fmaf(a.y, b.y, sv[1][1]);
                sv[1][2] = fmaf(a.y, b.z, sv[1][2]);
                sv[1][3] = fmaf(a.y, b.w, sv[1][3]);
                sv[2][0] = fmaf(a.z, b.x, sv[2][0]);
                sv[2][1] = fmaf(a.z, b.y, sv[2][1]);
                sv[2][2] = fmaf(a.z, b.z, sv[2][2]);
                sv[2][3] = fmaf(a.z, b.w, sv[2][3]);
                sv[3][0] = fmaf(a.w, b.x, sv[3][0]);
                sv[3][1] = fmaf(a.w, b.y, sv[3][1]);
                sv[3][2] = fmaf(a.w, b.z, sv[3][2]);
                sv[3][3] = fmaf(a.w, b.w, sv[3][3]);
            }

            // exp (bounded -> no max subtraction), per-row partial sums, W store
            int cb = s0 + tx * 4;
            #pragma unroll
            for (int i = 0; i < 4; i++) {
                float4 w;
                w.x = (cb + 0 >= ss && cb + 0 < se) ? fexp2(sv[i][0]) : 0.0f;
                w.y = (cb + 1 >= ss && cb + 1 < se) ? fexp2(sv[i][1]) : 0.0f;
                w.z = (cb + 2 >= ss && cb + 2 < se) ? fexp2(sv[i][2]) : 0.0f;
                w.w = (cb + 3 >= ss && cb + 3 < se) ? fexp2(sv[i][3]) : 0.0f;
                lpart[i] += (w.x + w.y) + (w.z + w.w);
                *(float4*)&Ws[ty * 4 + i][tx * 4] = w;
            }
            __syncthreads();

            // O accumulate: acc[seg] += Ws @ Vs  (float4 loads, 6 LDS.128 / 32 FMA)
            #pragma unroll 4
            for (int s = 0; s < 64; s += 4) {
                float4 va = *(const float4*)&Vs[h2][s];
                float4 vbp = *(const float4*)&Vs[h2 + 1][s];
                #pragma unroll
                for (int k = 0; k < 4; k++) {
                    float4 w = *(const float4*)&Ws[ty + 16 * k][s];
                    acc[seg][k][0] = fmaf(w.w, va.w, fmaf(w.z, va.z,
                                     fmaf(w.y, va.y, fmaf(w.x, va.x, acc[seg][k][0]))));
                    acc[seg][k][1] = fmaf(w.w, vbp.w, fmaf(w.z, vbp.z,
                                     fmaf(w.y, vbp.y, fmaf(w.x, vbp.x, acc[seg][k][1]))));
                }
            }
        }
        // reduce per-row l across the 16 column-threads (width-16 shuffle)
        #pragma unroll
        for (int i = 0; i < 4; i++) {
            float lf = lpart[i];
            #pragma unroll
            for (int o = 8; o; o >>= 1)
                lf += __shfl_xor_sync(0xffffffffu, lf, o, 16);
            if (tx == 0) sl_s[seg][ty * 4 + i] = lf;
        }
    }
    __syncthreads();

    // per-row reciprocal denominators for all 7 branches (once)
    if (tid < 64) {
        float lr[3] = {sl_s[0][tid], sl_s[1][tid], sl_s[2][tid]};
        #pragma unroll
        for (int br = 0; br < 7; br++) {
            int mask = bmask[br];
            float den = 0.0f;
            #pragma unroll
            for (int s = 0; s < 3; s++)
                if ((mask >> s) & 1) den += lr[s];
            srd[br][tid] = __frcp_rn(den);
        }
    }
    __syncthreads();

    // combine: 7 branch outputs straight from registers
    #pragma unroll
    for (int k = 0; k < 4; k++) {
        int r = ty + 16 * k;
        int t = t0 + r;
        int seg_t = (t < 300) ? 0 : (t < 550) ? 1 : 2;
        #pragma unroll
        for (int br = 0; br < 7; br++) {
            int mask = bmask[br];
            float2 val = make_float2(0.0f, 0.0f);
            if ((mask >> seg_t) & 1) {
                float num0 = 0.0f, num1 = 0.0f;
                #pragma unroll
                for (int s = 0; s < 3; s++) {
                    if ((mask >> s) & 1) {
                        num0 += acc[s][k][0];
                        num1 += acc[s][k][1];
                    }
                }
                float rd = srd[br][r];
                val.x = num0 * rd;
                val.y = num1 * rd;
            }
            *(float2*)&g_obuf[(size_t)br * 786432 + (size_t)bh * 24576 +
                              (size_t)t * 32 + h2] = val;
        }
    }
}

// ---------------- build G_i = sums of s_*_w column blocks ----------------
__global__ void __launch_bounds__(256) gmat_kernel(
    const float* __restrict__ sl, const float* __restrict__ sa,
    const float* __restrict__ sv)
{
    int idx = blockIdx.x * 256 + threadIdx.x;
    int i = idx >> 16;
    int y = (idx >> 8) & 255;
    int x = idx & 255;
    size_t r = (size_t)y * 1024;
    float v = 0.0f;
    switch (i) {
        case 0: v = sl[r + x]       + sa[r + x]       + sv[r + x];   break;
        case 1: v = sl[r + 256 + x] + sa[r + 256 + x];               break;
        case 2: v = sl[r + 512 + x] + sv[r + 256 + x];               break;
        case 3: v = sa[r + 512 + x] + sv[r + 512 + x];               break;
        case 4: v = sl[r + 768 + x];                                 break;
        case 5: v = sa[r + 768 + x];                                 break;
        case 6: v = sv[r + 768 + x];                                 break;
    }
    g_G[idx] = v;
}

// ---------------- bias fold, stage 1 ----------------
__global__ void __launch_bounds__(256) bias1_kernel(
    const float* __restrict__ out_b, const float* __restrict__ slb,
    const float* __restrict__ sab, const float* __restrict__ svb)
{
    int y = blockIdx.x;
    int tid = threadIdx.x;
    __shared__ float red[256];
    float p = 0.0f;
    #pragma unroll
    for (int i = 0; i < 7; i++)
        p += out_b[i * 256 + tid] * g_G[i * 65536 + y * 256 + tid];
    red[tid] = p;
    __syncthreads();
    for (int o = 128; o; o >>= 1) {
        if (tid < o) red[tid] += red[tid + o];
        __syncthreads();
    }
    if (tid == 0) g_c1[y] = red[0] + slb[y] + sab[y] + svb[y];
}

// ---------------- bias fold, stage 2 ----------------
__global__ void __launch_bounds__(256) bias2_kernel(
    const float* __restrict__ fb, const float* __restrict__ fw)
{
    int n = blockIdx.x;
    int tid = threadIdx.x;
    __shared__ float red[256];
    red[tid] = g_c1[tid] * fw[(size_t)n * 256 + tid];
    __syncthreads();
    for (int o = 128; o; o >>= 1) {
        if (tid < o) red[tid] += red[tid + o];
        __syncthreads();
    }
    if (tid == 0) g_biasv[n] = red[0] + fb[n];
}

// ---------------- final fused GEMM: out = sum_i o_i @ M_i + bias (dead-branch skip) ----------------
__global__ void __launch_bounds__(256) final_kernel(float* __restrict__ out)
{
    int m0 = blockIdx.y * 64, n0 = blockIdx.x * 32;
    __shared__ float As[32][68], Bs[32][36];
    int tid = threadIdx.x;
    int tx = tid & 15, ty = tid >> 4;

    int tb0 = m0 >> 2, tb1 = (m0 + 63) >> 2;
    int bm = 0;
    #pragma unroll
    for (int br = 0; br < 7; br++) {
        int mk = c_bmask[br];
        #pragma unroll
        for (int s = 0; s < 3; s++)
            if (((mk >> s) & 1) && tb0 < c_segE[s] && tb1 >= c_segS[s]) bm |= 1 << br;
    }

    float acc[4][2] = {};
    for (int k0 = 0; k0 < 1792; k0 += 32) {
        int ibr = k0 >> 8;
        if (!((bm >> ibr) & 1)) continue;
        int h = (k0 & 255) >> 5;
        const float* Abase = g_obuf + (size_t)ibr * 786432 + (size_t)h * 24576;
        #pragma unroll
        for (int i = 0; i < 8; i++) {
            int idx = tid + i * 256;
            int mm = idx >> 5, kk = idx & 31;
            int m = m0 + mm;
            int t = m >> 2, b = m & 3;
            As[kk][mm] = Abase[(size_t)b * 196608 + (size_t)t * 32 + kk];
        }
        #pragma unroll
        for (int i = 0; i < 4; i++) {
            int idx = tid + i * 256;
            int nn = idx >> 5, kk = idx & 31;
            Bs[kk][nn] = g_MTcat[(size_t)(n0 + nn) * 1792 + k0 + kk];
        }
        __syncthreads();
        #pragma unroll
        for (int kk = 0; kk < 32; kk++) {
            float4 a = *(const float4*)&As[kk][ty * 4];
            float2 b = *(const float2*)&Bs[kk][tx * 2];
            acc[0][0] = fmaf(a.x, b.x, acc[0][0]);
            acc[0][1] = fmaf(a.x, b.y, acc[0][1]);
            acc[1][0] = fmaf(a.y, b.x, acc[1][0]);
            acc[1][1] = fmaf(a.y, b.y, acc[1][1]);
            acc[2][0] = fmaf(a.z, b.x, acc[2][0]);
            acc[2][1] = fmaf(a.z, b.y, acc[2][1]);
            acc[3][0] = fmaf(a.w, b.x, acc[3][0]);
            acc[3][1] = fmaf(a.w, b.y, acc[3][1]);
        }
        __syncthreads();
    }
    #pragma unroll
    for (int i = 0; i < 4; i++) {
        int m = m0 + ty * 4 + i;
        #pragma unroll
        for (int j = 0; j < 2; j++) {
            int n = n0 + tx * 2 + j;
            out[(size_t)m * 256 + n] = acc[i][j] + g_biasv[n];
        }
    }
}

// ---------------- launch: fork precompute chain onto side stream ----------------
extern "C" void kernel_launch(void* const* d_in, const int* in_sizes, int n_in,
                              void* d_out, int out_size)
{
    const float* query     = (const float*)d_in[0];
    const float* key       = (const float*)d_in[1];
    const float* value     = (const float*)d_in[2];
    const float* in_proj_w = (const float*)d_in[3];
    const float* in_proj_b = (const float*)d_in[4];
    const float* out_w     = (const float*)d_in[5];
    const float* out_b     = (const float*)d_in[6];
    const float* s_l_w     = (const float*)d_in[7];
    const float* s_l_b     = (const float*)d_in[8];
    const float* s_a_w     = (const float*)d_in[9];
    const float* s_a_b     = (const float*)d_in[10];
    const float* s_v_w     = (const float*)d_in[11];
    const float* s_v_b     = (const float*)d_in[12];
    const float* final_w   = (const float*)d_in[13];
    const float* final_b   = (const float*)d_in[14];
    float* out = (float*)d_out;
    (void)in_sizes; (void)n_in; (void)out_size;

    float *p_G, *p_tmpT, *p_MTcat;
    cudaGetSymbolAddress((void**)&p_G,      g_G);
    cudaGetSymbolAddress((void**)&p_tmpT,   g_tmpT);
    cudaGetSymbolAddress((void**)&p_MTcat,  g_MTcat);

    // lazy one-time stream/event setup (no device memory involved)
    static cudaStream_t s_side = nullptr;
    static cudaEvent_t ev_fork = nullptr, ev_join = nullptr;
    if (s_side == nullptr) {
        cudaStreamCreateWithFlags(&s_side, cudaStreamNonBlocking);
        cudaEventCreateWithFlags(&ev_fork, cudaEventDisableTiming);
        cudaEventCreateWithFlags(&ev_join, cudaEventDisableTiming);
    }

    // fork: weight-only precompute chain runs concurrently with proj+flash
    cudaEventRecord(ev_fork, 0);
    cudaStreamWaitEvent(s_side, ev_fork, 0);

    gmat_kernel<<<1792, 256, 0, s_side>>>(s_l_w, s_a_w, s_v_w);
    gemm_small<<<dim3(8, 8, 7), 256, 0, s_side>>>(
        out_w, 1, 256, 65536,
        p_G, 256, 1, 65536,
        p_tmpT, 256, 65536, 256);
    gemm_small<<<dim3(8, 8, 7), 256, 0, s_side>>>(
        final_w, 256, 1, 0,
        p_tmpT, 256, 1, 65536,
        p_MTcat, 1792, 256, 256);
    bias1_kernel<<<256, 256, 0, s_side>>>(out_b, s_l_b, s_a_b, s_v_b);
    bias2_kernel<<<256, 256, 0, s_side>>>(final_b, final_w);
    cudaEventRecord(ev_join, s_side);

    // main stream: activation path
    proj_kernel<<<dim3(4, 48, 3), 256>>>(query, key, value, in_proj_w, in_proj_b);
    flash_kernel<<<dim3(12, 32), 256>>>();

    // join, then final GEMM
    cudaStreamWaitEvent(0, ev_join, 0);
    final_kernel<<<dim3(8, 48), 256>>>(out);
}

// round 8
// speedup vs baseline: 1.0769x; 1.0769x over previous
#include <cuda_runtime.h>
#include <math.h>

// Problem constants: T=768, B=4, E=256, H=8, HD=32, 32 "bh" heads.
// Q scale folded with log2(e): scores arrive in log2 domain, exp(s) == 2^s'.
#define QSCALE 0.25500917392938054f   // (1/sqrt(32)) * log2(e)

// ---------------- scratch (static device globals; no allocation) ----------------
__device__ float g_q[786432];        // [bh=32][t=768][hd=32]
__device__ float g_k[786432];
__device__ float g_v[786432];
__device__ float g_obuf[5505024];    // [branch=7][bh=32][t=768][hd=32]
__device__ float g_G[458752];        // [7][y=256][x=256]
__device__ float g_tmpT[458752];     // [7][a=256][y=256]
__device__ float g_MTcat[458752];    // [n=256][k=1792]
__device__ float g_c1[256];
__device__ float g_biasv[256];

// Segments partition the columns: L=[0,300) A=[300,550) V=[550,768)
__constant__ int c_segS[3] = {0, 300, 550};
__constant__ int c_segE[3] = {300, 550, 768};
// branch -> segment bitmask: lav, la, lv, av, l, a, v
__constant__ int c_bmask[7] = {7, 3, 5, 6, 1, 2, 4};

// FMA-pipe 2^x (no MUFU). |x| < ~80, rel err ~1e-7 (deg-6 Taylor on [-0.5,0.5]).
__device__ __forceinline__ float fexp2(float x)
{
    float z = x + 12582912.0f;            // 1.5*2^23: round-to-nearest-int trick
    int   n = __float_as_int(z);          // low bits hold round(x)
    float f = x - (z - 12582912.0f);      // frac in [-0.5, 0.5], exact
    float p = 1.5402387e-4f;
    p = fmaf(p, f, 1.3333558e-3f);
    p = fmaf(p, f, 9.6181291e-3f);
    p = fmaf(p, f, 5.5504109e-2f);
    p = fmaf(p, f, 2.4022651e-1f);
    p = fmaf(p, f, 6.9314718e-1f);
    p = fmaf(p, f, 1.0f);
    return __int_as_float(__float_as_int(p) + (n << 23));
}

// ---------------- small tiled SGEMM (32x32 tiles, K-step 32), coalesced ----------------
__global__ void __launch_bounds__(256) gemm_small(
    const float* __restrict__ A, int a_sm, int a_sk, int a_bz,
    const float* __restrict__ B, int b_sn, int b_sk, int b_bz,
    float* __restrict__ C, int c_sm, int c_bz,
    int K)
{
    A += (size_t)blockIdx.z * a_bz;
    B += (size_t)blockIdx.z * b_bz;
    C += (size_t)blockIdx.z * c_bz;
    int m0 = blockIdx.y * 32, n0 = blockIdx.x * 32;
    __shared__ float As[32][36], Bs[32][36];
    int tid = threadIdx.x;
    int tx = tid & 15, ty = tid >> 4;
    float acc[2][2] = {};
    for (int k0 = 0; k0 < K; k0 += 32) {
        if (a_sk == 1) {   // k contiguous: kk fastest across tid
            #pragma unroll
            for (int i = 0; i < 4; i++) {
                int idx = tid + i * 256;
                int mm = idx >> 5, kk = idx & 31;
                As[kk][mm] = A[(size_t)(m0 + mm) * a_sm + (k0 + kk)];
            }
        } else {           // m contiguous: mm fastest across tid
            #pragma unroll
            for (int i = 0; i < 4; i++) {
                int idx = tid + i * 256;
                int mm = idx & 31, kk = idx >> 5;
                As[kk][mm] = A[(size_t)(m0 + mm) + (size_t)(k0 + kk) * a_sk];
            }
        }
        if (b_sk == 1) {
            #pragma unroll
            for (int i = 0; i < 4; i++) {
                int idx = tid + i * 256;
                int mm = idx >> 5, kk = idx & 31;
                Bs[kk][mm] = B[(size_t)(n0 + mm) * b_sn + (k0 + kk)];
            }
        } else {
            #pragma unroll
            for (int i = 0; i < 4; i++) {
                int idx = tid + i * 256;
                int mm = idx & 31, kk = idx >> 5;
                Bs[kk][mm] = B[(size_t)(n0 + mm) + (size_t)(k0 + kk) * b_sk];
            }
        }
        __syncthreads();
        #pragma unroll
        for (int kk = 0; kk < 32; kk++) {
            float2 a = *(const float2*)&As[kk][ty * 2];
            float2 b = *(const float2*)&Bs[kk][tx * 2];
            acc[0][0] = fmaf(a.x, b.x, acc[0][0]);
            acc[0][1] = fmaf(a.x, b.y, acc[0][1]);
            acc[1][0] = fmaf(a.y, b.x, acc[1][0]);
            acc[1][1] = fmaf(a.y, b.y, acc[1][1]);
        }
        __syncthreads();
    }
    #pragma unroll
    for (int i = 0; i < 2; i++)
        #pragma unroll
        for (int j = 0; j < 2; j++)
            C[(size_t)(m0 + ty * 2 + i) * c_sm + (n0 + tx * 2 + j)] = acc[i][j];
}

// ---------------- QKV projection, scattered to head-major ----------------
__global__ void __launch_bounds__(256) proj_kernel(
    const float* __restrict__ q_in, const float* __restrict__ k_in,
    const float* __restrict__ v_in, const float* __restrict__ W,
    const float* __restrict__ bias)
{
    int z = blockIdx.z;
    const float* A = (z == 0) ? q_in : (z == 1) ? k_in : v_in;
    float* dst = (z == 0) ? g_q : (z == 1) ? g_k : g_v;
    const float* Bw = W + (size_t)z * 65536;
    const float* bz = bias + z * 256;
    float scale = (z == 0) ? QSCALE : 1.0f;

    int m0 = blockIdx.y * 64, n0 = blockIdx.x * 64;
    __shared__ float As[16][68], Bs[16][68];
    int tid = threadIdx.x;
    int tx = tid & 15, ty = tid >> 4;
    float acc[4][4] = {};
    for (int k0 = 0; k0 < 256; k0 += 16) {
        #pragma unroll
        for (int i = 0; i < 4; i++) {
            int idx = tid + i * 256;
            int mm = idx >> 4, kk = idx & 15;
            As[kk][mm] = A[(size_t)(m0 + mm) * 256 + (k0 + kk)];
            Bs[kk][mm] = Bw[(size_t)(n0 + mm) * 256 + (k0 + kk)];
        }
        __syncthreads();
        #pragma unroll
        for (int kk = 0; kk < 16; kk++) {
            float4 a = *(const float4*)&As[kk][ty * 4];
            float4 b = *(const float4*)&Bs[kk][tx * 4];
            acc[0][0] = fmaf(a.x, b.x, acc[0][0]);
            acc[0][1] = fmaf(a.x, b.y, acc[0][1]);
            acc[0][2] = fmaf(a.x, b.z, acc[0][2]);
            acc[0][3] = fmaf(a.x, b.w, acc[0][3]);
            acc[1][0] = fmaf(a.y, b.x, acc[1][0]);
            acc[1][1] = fmaf(a.y, b.y, acc[1][1]);
            acc[1][2] = fmaf(a.y, b.z, acc[1][2]);
            acc[1][3] = fmaf(a.y, b.w, acc[1][3]);
            acc[2][0] = fmaf(a.z, b.x, acc[2][0]);
            acc[2][1] = fmaf(a.z, b.y, acc[2][1]);
            acc[2][2] = fmaf(a.z, b.z, acc[2][2]);
            acc[2][3] = fmaf(a.z, b.w, acc[2][3]);
            acc[3][0] = fmaf(a.w, b.x, acc[3][0]);
            acc[3][1] = fmaf(a.w, b.y, acc[3][1]);
            acc[3][2] = fmaf(a.w, b.z, acc[3][2]);
            acc[3][3] = fmaf(a.w, b.w, acc[3][3]);
        }
        __syncthreads();
    }
    #pragma unroll
    for (int i = 0; i < 4; i++) {
        int m = m0 + ty * 4 + i;
        int t = m >> 2, b = m & 3;
        #pragma unroll
        for (int j = 0; j < 4; j++) {
            int n = n0 + tx * 4 + j;
            int h = n >> 5, hd = n & 31;
            float val = (acc[i][j] + bz[n]) * scale;
            dst[(size_t)((b * 8 + h) * 768 + t) * 32 + hd] = val;
        }
    }
}

// ---------------- fully fused flash attention + branch combine ----------------
// Double-buffered K/V tiles: prefetch next tile during S-compute; 2 syncs/tile.
__global__ void __launch_bounds__(256) flash_kernel()
{
    const int segS[3] = {0, 300, 550};
    const int segE[3] = {300, 550, 768};
    const int bmask[7] = {7, 3, 5, 6, 1, 2, 4};

    int bh = blockIdx.y, t0 = blockIdx.x * 64;
    int tid = threadIdx.x;
    int tx = tid & 15, ty = tid >> 4;   // S mapping: rows ty*4+i, cols tx*4+j
    int h2 = tx * 2;                    // PV mapping: rows ty+16k, hd pair h2

    __shared__ float QsT[32][68];
    __shared__ float KsT[2][32][68];
    __shared__ float Vs[2][32][68];
    __shared__ float Ws[64][68];
    __shared__ float sl_s[3][64];
    __shared__ float srd[7][64];

    const float* qbase = g_q + (size_t)bh * 24576 + (size_t)t0 * 32;
    const float* kb = g_k + (size_t)bh * 24576;
    const float* vb = g_v + (size_t)bh * 24576;

    #pragma unroll
    for (int i = 0; i < 8; i++) {
        int idx = tid + i * 256;
        int r = idx >> 5, kk = idx & 31;
        QsT[kk][r] = qbase[r * 32 + kk];
    }

    float acc[3][4][2] = {};

    int ldr = (tid >> 5);          // 0..7: loader row group
    int ldk = tid & 31;            // 0..31
    #pragma unroll
    for (int seg = 0; seg < 3; seg++) {
        int ss = segS[seg], se = segE[seg];
        int ts = ss >> 6, te = (se + 63) >> 6;
        float lpart[4];
        #pragma unroll
        for (int i = 0; i < 4; i++) lpart[i] = 0.0f;

        // preload first tile of segment into buffer 0
        {
            int s0 = ts * 64;
            #pragma unroll
            for (int i = 0; i < 4; i++) {
                int r = ldr + i * 8;
                KsT[0][ldk][r]          = kb[(size_t)(s0 + r) * 32 + ldk];
                KsT[0][ldk][r + 32]     = kb[(size_t)(s0 + r + 32) * 32 + ldk];
                Vs[0][ldk][r]           = vb[(size_t)(s0 + r) * 32 + ldk];
                Vs[0][ldk][r + 32]      = vb[(size_t)(s0 + r + 32) * 32 + ldk];
            }
        }
        __syncthreads();

        int buf = 0;
        for (int st = ts; st < te; st++) {
            int s0 = st * 64;
            // prefetch next tile into the other buffer
            if (st + 1 < te) {
                int s1 = s0 + 64;
                int nb = buf ^ 1;
                #pragma unroll
                for (int i = 0; i < 4; i++) {
                    int r = ldr + i * 8;
                    KsT[nb][ldk][r]      = kb[(size_t)(s1 + r) * 32 + ldk];
                    KsT[nb][ldk][r + 32] = kb[(size_t)(s1 + r + 32) * 32 + ldk];
                    Vs[nb][ldk][r]       = vb[(size_t)(s1 + r) * 32 + ldk];
                    Vs[nb][ldk][r + 32]  = vb[(size_t)(s1 + r + 32) * 32 + ldk];
                }
            }

            // S tile 4x4: rows ty*4+i, cols tx*4+j
            float sv[4][4] = {};
            #pragma unroll
            for (int kk = 0; kk < 32; kk++) {
                float4 a = *(const float4*)&QsT[kk][ty * 4];
                float4 b = *(const float4*)&KsT[buf][kk][tx * 4];
                sv[0][0] = fmaf(a.x, b.x, sv[0][0]);
                sv[0][1] = fmaf(a.x, b.y, sv[0][1]);
                sv[0][2] = fmaf(a.x, b.z, sv[0][2]);
                sv[0][3] = fmaf(a.x, b.w, sv[0][3]);
                sv[1][0] = fmaf(a.y, b.x, sv[1][0]);
                sv[1][1] = fmaf(a.y, b.y, sv[1][1]);
                sv[1][2] = fmaf(a.y, b.z, sv[1][2]);
                sv[1][3] = fmaf(a.y, b.w, sv[1][3]);
                sv[2][0] = fmaf(a.z, b.x, sv[2][0]);
                sv[2][1] = fmaf(a.z, b.y, sv[2][1]);
                sv[2][2] = fmaf(a.z, b.z, sv[2][2]);
                sv[2][3] = fmaf(a.z, b.w, sv[2][3]);
                sv[3][0] = fmaf(a.w, b.x, sv[3][0]);
                sv[3][1] = fmaf(a.w, b.y, sv[3][1]);
                sv[3][2] = fmaf(a.w, b.z, sv[3][2]);
                sv[3][3] = fmaf(a.w, b.w, sv[3][3]);
            }

            // exp (bounded -> no max subtraction), per-row partial sums, W store
            int cb = s0 + tx * 4;
            #pragma unroll
            for (int i = 0; i < 4; i++) {
                float4 w;
                w.x = (cb + 0 >= ss && cb + 0 < se) ? fexp2(sv[i][0]) : 0.0f;
                w.y = (cb + 1 >= ss && cb + 1 < se) ? fexp2(sv[i][1]) : 0.0f;
                w.z = (cb + 2 >= ss && cb + 2 < se) ? fexp2(sv[i][2]) : 0.0f;
                w.w = (cb + 3 >= ss && cb + 3 < se) ? fexp2(sv[i][3]) : 0.0f;
                lpart[i] += (w.x + w.y) + (w.z + w.w);
                *(float4*)&Ws[ty * 4 + i][tx * 4] = w;
            }
            __syncthreads();   // Ws visible; prefetch STS also complete

            // O accumulate: acc[seg] += Ws @ Vs  (float4 loads)
            #pragma unroll 4
            for (int s = 0; s < 64; s += 4) {
                float4 va = *(const float4*)&Vs[buf][h2][s];
                float4 vbp = *(const float4*)&Vs[buf][h2 + 1][s];
                #pragma unroll
                for (int k = 0; k < 4; k++) {
                    float4 w = *(const float4*)&Ws[ty + 16 * k][s];
                    acc[seg][k][0] = fmaf(w.w, va.w, fmaf(w.z, va.z,
                                     fmaf(w.y, va.y, fmaf(w.x, va.x, acc[seg][k][0]))));
                    acc[seg][k][1] = fmaf(w.w, vbp.w, fmaf(w.z, vbp.z,
                                     fmaf(w.y, vbp.y, fmaf(w.x, vbp.x, acc[seg][k][1]))));
                }
            }
            __syncthreads();   // protect Ws before next tile's store
            buf ^= 1;
        }
        // reduce per-row l across the 16 column-threads (width-16 shuffle)
        #pragma unroll
        for (int i = 0; i < 4; i++) {
            float lf = lpart[i];
            #pragma unroll
            for (int o = 8; o; o >>= 1)
                lf += __shfl_xor_sync(0xffffffffu, lf, o, 16);
            if (tx == 0) sl_s[seg][ty * 4 + i] = lf;
        }
    }
    __syncthreads();

    // per-row reciprocal denominators for all 7 branches (once)
    if (tid < 64) {
        float lr[3] = {sl_s[0][tid], sl_s[1][tid], sl_s[2][tid]};
        #pragma unroll
        for (int br = 0; br < 7; br++) {
            int mask = bmask[br];
            float den = 0.0f;
            #pragma unroll
            for (int s = 0; s < 3; s++)
                if ((mask >> s) & 1) den += lr[s];
            srd[br][tid] = __frcp_rn(den);
        }
    }
    __syncthreads();

    // combine: 7 branch outputs straight from registers
    #pragma unroll
    for (int k = 0; k < 4; k++) {
        int r = ty + 16 * k;
        int t = t0 + r;
        int seg_t = (t < 300) ? 0 : (t < 550) ? 1 : 2;
        #pragma unroll
        for (int br = 0; br < 7; br++) {
            int mask = bmask[br];
            float2 val = make_float2(0.0f, 0.0f);
            if ((mask >> seg_t) & 1) {
                float num0 = 0.0f, num1 = 0.0f;
                #pragma unroll
                for (int s = 0; s < 3; s++) {
                    if ((mask >> s) & 1) {
                        num0 += acc[s][k][0];
                        num1 += acc[s][k][1];
                    }
                }
                float rd = srd[br][r];
                val.x = num0 * rd;
                val.y = num1 * rd;
            }
            *(float2*)&g_obuf[(size_t)br * 786432 + (size_t)bh * 24576 +
                              (size_t)t * 32 + h2] = val;
        }
    }
}

// ---------------- build G_i = sums of s_*_w column blocks ----------------
__global__ void __launch_bounds__(256) gmat_kernel(
    const float* __restrict__ sl, const float* __restrict__ sa,
    const float* __restrict__ sv)
{
    int idx = blockIdx.x * 256 + threadIdx.x;
    int i = idx >> 16;
    int y = (idx >> 8) & 255;
    int x = idx & 255;
    size_t r = (size_t)y * 1024;
    float v = 0.0f;
    switch (i) {
        case 0: v = sl[r + x]       + sa[r + x]       + sv[r + x];   break;
        case 1: v = sl[r + 256 + x] + sa[r + 256 + x];               break;
        case 2: v = sl[r + 512 + x] + sv[r + 256 + x];               break;
        case 3: v = sa[r + 512 + x] + sv[r + 512 + x];               break;
        case 4: v = sl[r + 768 + x];                                 break;
        case 5: v = sa[r + 768 + x];                                 break;
        case 6: v = sv[r + 768 + x];                                 break;
    }
    g_G[idx] = v;
}

// ---------------- bias fold, stage 1 ----------------
__global__ void __launch_bounds__(256) bias1_kernel(
    const float* __restrict__ out_b, const float* __restrict__ slb,
    const float* __restrict__ sab, const float* __restrict__ svb)
{
    int y = blockIdx.x;
    int tid = threadIdx.x;
    __shared__ float red[256];
    float p = 0.0f;
    #pragma unroll
    for (int i = 0; i < 7; i++)
        p += out_b[i * 256 + tid] * g_G[i * 65536 + y * 256 + tid];
    red[tid] = p;
    __syncthreads();
    for (int o = 128; o; o >>= 1) {
        if (tid < o) red[tid] += red[tid + o];
        __syncthreads();
    }
    if (tid == 0) g_c1[y] = red[0] + slb[y] + sab[y] + svb[y];
}

// ---------------- bias fold, stage 2 ----------------
__global__ void __launch_bounds__(256) bias2_kernel(
    const float* __restrict__ fb, const float* __restrict__ fw)
{
    int n = blockIdx.x;
    int tid = threadIdx.x;
    __shared__ float red[256];
    red[tid] = g_c1[tid] * fw[(size_t)n * 256 + tid];
    __syncthreads();
    for (int o = 128; o; o >>= 1) {
        if (tid < o) red[tid] += red[tid + o];
        __syncthreads();
    }
    if (tid == 0) g_biasv[n] = red[0] + fb[n];
}

// ---------------- final fused GEMM: out = sum_i o_i @ M_i + bias (dead-branch skip) ----------------
__global__ void __launch_bounds__(256) final_kernel(float* __restrict__ out)
{
    int m0 = blockIdx.y * 64, n0 = blockIdx.x * 32;
    __shared__ float As[32][68], Bs[32][36];
    int tid = threadIdx.x;
    int tx = tid & 15, ty = tid >> 4;

    int tb0 = m0 >> 2, tb1 = (m0 + 63) >> 2;
    int bm = 0;
    #pragma unroll
    for (int br = 0; br < 7; br++) {
        int mk = c_bmask[br];
        #pragma unroll
        for (int s = 0; s < 3; s++)
            if (((mk >> s) & 1) && tb0 < c_segE[s] && tb1 >= c_segS[s]) bm |= 1 << br;
    }

    float acc[4][2] = {};
    for (int k0 = 0; k0 < 1792; k0 += 32) {
        int ibr = k0 >> 8;
        if (!((bm >> ibr) & 1)) continue;
        int h = (k0 & 255) >> 5;
        const float* Abase = g_obuf + (size_t)ibr * 786432 + (size_t)h * 24576;
        #pragma unroll
        for (int i = 0; i < 8; i++) {
            int idx = tid + i * 256;
            int mm = idx >> 5, kk = idx & 31;
            int m = m0 + mm;
            int t = m >> 2, b = m & 3;
            As[kk][mm] = Abase[(size_t)b * 196608 + (size_t)t * 32 + kk];
        }
        #pragma unroll
        for (int i = 0; i < 4; i++) {
            int idx = tid + i * 256;
            int nn = idx >> 5, kk = idx & 31;
            Bs[kk][nn] = g_MTcat[(size_t)(n0 + nn) * 1792 + k0 + kk];
        }
        __syncthreads();
        #pragma unroll
        for (int kk = 0; kk < 32; kk++) {
            float4 a = *(const float4*)&As[kk][ty * 4];
            float2 b = *(const float2*)&Bs[kk][tx * 2];
            acc[0][0] = fmaf(a.x, b.x, acc[0][0]);
            acc[0][1] = fmaf(a.x, b.y, acc[0][1]);
            acc[1][0] = fmaf(a.y, b.x, acc[1][0]);
            acc[1][1] = fmaf(a.y, b.y, acc[1][1]);
            acc[2][0] = fmaf(a.z, b.x, acc[2][0]);
            acc[2][1] = fmaf(a.z, b.y, acc[2][1]);
            acc[3][0] = fmaf(a.w, b.x, acc[3][0]);
            acc[3][1] = fmaf(a.w, b.y, acc[3][1]);
        }
        __syncthreads();
    }
    #pragma unroll
    for (int i = 0; i < 4; i++) {
        int m = m0 + ty * 4 + i;
        #pragma unroll
        for (int j = 0; j < 2; j++) {
            int n = n0 + tx * 2 + j;
            out[(size_t)m * 256 + n] = acc[i][j] + g_biasv[n];
        }
    }
}

// ---------------- launch (serial; stream overlap regressed in R7) ----------------
extern "C" void kernel_launch(void* const* d_in, const int* in_sizes, int n_in,
                              void* d_out, int out_size)
{
    const float* query     = (const float*)d_in[0];
    const float* key       = (const float*)d_in[1];
    const float* value     = (const float*)d_in[2];
    const float* in_proj_w = (const float*)d_in[3];
    const float* in_proj_b = (const float*)d_in[4];
    const float* out_w     = (const float*)d_in[5];
    const float* out_b     = (const float*)d_in[6];
    const float* s_l_w     = (const float*)d_in[7];
    const float* s_l_b     = (const float*)d_in[8];
    const float* s_a_w     = (const float*)d_in[9];
    const float* s_a_b     = (const float*)d_in[10];
    const float* s_v_w     = (const float*)d_in[11];
    const float* s_v_b     = (const float*)d_in[12];
    const float* final_w   = (const float*)d_in[13];
    const float* final_b   = (const float*)d_in[14];
    float* out = (float*)d_out;
    (void)in_sizes; (void)n_in; (void)out_size;

    float *p_G, *p_tmpT, *p_MTcat;
    cudaGetSymbolAddress((void**)&p_G,      g_G);
    cudaGetSymbolAddress((void**)&p_tmpT,   g_tmpT);
    cudaGetSymbolAddress((void**)&p_MTcat,  g_MTcat);

    // 1. q/k/v projections -> head-major (q scaled by 1/sqrt(hd) * log2 e)
    proj_kernel<<<dim3(4, 48, 3), 256>>>(query, key, value, in_proj_w, in_proj_b);

    // 2. fused flash attention + branch combine (double-buffered K/V)
    flash_kernel<<<dim3(12, 32), 256>>>();

    // 3a. G_i
    gmat_kernel<<<1792, 256>>>(s_l_w, s_a_w, s_v_w);

    // 3b. tmpT[i][a][y] = sum_x out_w[i][x][a] * G_i[y][x]
    gemm_small<<<dim3(8, 8, 7), 256>>>(
        out_w, 1, 256, 65536,
        p_G, 256, 1, 65536,
        p_tmpT, 256, 65536, 256);

    // 3c. MTcat[n][i*256+a] = sum_y final_w[n][y] * tmpT[i][a][y]
    gemm_small<<<dim3(8, 8, 7), 256>>>(
        final_w, 256, 1, 0,
        p_tmpT, 256, 1, 65536,
        p_MTcat, 1792, 256, 256);

    // 3d. fold biases (parallel two-stage)
    bias1_kernel<<<256, 256>>>(out_b, s_l_b, s_a_b, s_v_b);
    bias2_kernel<<<256, 256>>>(final_b, final_w);

    // 4. out = sum_i o_i @ M_i + bias   (M=3072, N=256, K<=1792 with dead-branch skip)
    final_kernel<<<dim3(8, 48), 256>>>(out);
}